// round 14
// baseline (speedup 1.0000x reference)
#include <cuda_runtime.h>
#include <cuda_bf16.h>
#include <mma.h>
#include <cstdint>

using namespace nvcuda;

#define NSPECIES 4
#define FDIM 128
#define HDIM 64
#define MAXN 2000000
#define TM 64                 // atoms per tile (per group)
#define NGROUPS 4
#define NTHREADS 512
#define SA 72                 // bf16 tile stride (elements): ldmatrix conflict-free
#define SAO 68                // fp32 O-tile stride (elements): LDS.128 conflict-free

// ---------------- device scratch ----------------
__device__ int g_meta[8];     // [0..3] counts, [4..7] scatter cursors
__device__ int g_is64;
__device__ int g_sorted[MAXN];

// ---------------- helpers ----------------
__device__ __forceinline__ float fast_tanh(float x) {
    // tanh(x) = 1 - 2/(exp(2x)+1); stable at +/-inf.
    float e = __expf(2.0f * x);
    return 1.0f - __fdividef(2.0f, e + 1.0f);
}
__device__ __forceinline__ unsigned bf2pack(float flo, float fhi) {
    unsigned r;
    asm("cvt.rn.bf16x2.f32 %0, %1, %2;" : "=r"(r) : "f"(fhi), "f"(flo));
    return r;
}
__device__ __forceinline__ float2 bf2unpack(unsigned u) {
    __nv_bfloat162 h = *reinterpret_cast<__nv_bfloat162*>(&u);
    return __bfloat1622float2(h);
}
__device__ __forceinline__ void split_pair(float f0, float f1,
                                           unsigned& hi, unsigned& lo) {
    hi = bf2pack(f0, f1);
    float2 b = bf2unpack(hi);
    lo = bf2pack(f0 - b.x, f1 - b.y);
}

// ---------------- preproc (validated) ----------------
__global__ void init_kernel(const long long* __restrict__ sp, int n) {
    __shared__ int s_ok;
    if (threadIdx.x == 0) s_ok = 1;
    __syncthreads();
    const int m = (n / 2 < 128) ? n / 2 : 128;
    if (threadIdx.x < m) {
        long long v = sp[threadIdx.x];
        if (v < 0 || v > 3) atomicExch(&s_ok, 0);
    }
    __syncthreads();
    if (threadIdx.x == 0) g_is64 = s_ok;
    if (threadIdx.x < 8) g_meta[threadIdx.x] = 0;
}
__device__ __forceinline__ int load_sp(const void* sp, int i, int is64) {
    return is64 ? (int)((const long long*)sp)[i] : ((const int*)sp)[i];
}
__global__ void hist_kernel(const void* __restrict__ sp, int n) {
    __shared__ int hs[NSPECIES];
    if (threadIdx.x < NSPECIES) hs[threadIdx.x] = 0;
    __syncthreads();
    const int is64 = g_is64;
    const int stride = gridDim.x * blockDim.x;
    for (int i = blockIdx.x * blockDim.x + threadIdx.x; i < n; i += stride)
        atomicAdd(&hs[load_sp(sp, i, is64)], 1);
    __syncthreads();
    if (threadIdx.x < NSPECIES) atomicAdd(&g_meta[threadIdx.x], hs[threadIdx.x]);
}
__global__ void scatter_kernel(const void* __restrict__ sp, int n) {
    const int is64 = g_is64;
    int offs[NSPECIES];
    { int a = 0;
      #pragma unroll
      for (int s = 0; s < NSPECIES; s++) { offs[s] = a; a += g_meta[s]; } }
    const int stride = gridDim.x * blockDim.x;
    const int lane = threadIdx.x & 31;
    for (int i = blockIdx.x * blockDim.x + threadIdx.x; i < n; i += stride) {
        int s = load_sp(sp, i, is64);
        unsigned act = __activemask();
        unsigned peers = __match_any_sync(act, s);
        int leader = __ffs(peers) - 1;
        int cnt = __popc(peers);
        int base = 0;
        if (lane == leader) base = atomicAdd(&g_meta[NSPECIES + s], cnt);
        base = __shfl_sync(peers, base, leader);
        g_sorted[offs[s] + base + __popc(peers & ((1u << lane) - 1u))] = i;
    }
}

// ---------------- SMEM byte layout ----------------
#define BY_W1H 0
#define BY_W1L (BY_W1H + FDIM * SA * 2)            // 18432
#define BY_W2H (BY_W1L + FDIM * SA * 2)            // 36864
#define BY_W2L (BY_W2H + HDIM * SA * 2)            // 46080
#define BY_BUF (BY_W2L + HDIM * SA * 2)            // 55296; bf16 A/H per group
#define BY_OF  (BY_BUF + NGROUPS * TM * SA * 4)    // 129024; fp32 O per group
#define BY_B1  (BY_OF + NGROUPS * TM * SAO * 4)    // 198656
#define BY_B2  (BY_B1 + HDIM * 4)
#define BY_W3  (BY_B2 + HDIM * 4)
#define BY_B3  (BY_W3 + HDIM * 4)                  // 199424
#define BY_EP  (BY_B3 + 16)                        // 199440
#define SMEM_BYTES (BY_EP + NGROUPS * TM * 4)      // 200464

extern __shared__ char smc[];

#define GBAR(id) asm volatile("bar.sync %0, 128;" :: "r"(id) : "memory")

__global__ void __launch_bounds__(NTHREADS, 1)
wmma_mlp_kernel(const float* __restrict__ feats,
                const float* __restrict__ W1, const float* __restrict__ b1,
                const float* __restrict__ W2, const float* __restrict__ b2,
                const float* __restrict__ W3, const float* __restrict__ b3,
                float* __restrict__ out)
{
    const int tid  = threadIdx.x;
    const int g    = tid >> 7;            // group 0..3
    const int gid  = tid & 127;
    const int wg   = gid >> 5;            // warp in group 0..3
    const int wj   = wg >> 1;             // M-half (2 tiles)
    const int wi   = wg & 1;              // N-half (2 tiles)
    const int row  = gid & 63;            // atom row for scalar passes
    const int half = gid >> 6;            // column half 0/1
    const int barid = 1 + g;

    __nv_bfloat16* W1h = (__nv_bfloat16*)(smc + BY_W1H);
    __nv_bfloat16* W1l = (__nv_bfloat16*)(smc + BY_W1L);
    __nv_bfloat16* W2h = (__nv_bfloat16*)(smc + BY_W2H);
    __nv_bfloat16* W2l = (__nv_bfloat16*)(smc + BY_W2L);
    __nv_bfloat16* Bh = (__nv_bfloat16*)(smc + BY_BUF + g * TM * SA * 4);  // [64][SA]
    __nv_bfloat16* Bl = Bh + TM * SA;                                       // [64][SA]
    float* Of  = (float*)(smc + BY_OF) + g * TM * SAO;                      // [64][SAO]
    float* b1f = (float*)(smc + BY_B1);
    float* b2f = (float*)(smc + BY_B2);
    float* w3f = (float*)(smc + BY_W3);
    float* b3f = (float*)(smc + BY_B3);
    float* EP  = (float*)(smc + BY_EP) + g * TM;

    // ---- species / tile / quad tables ----
    int beg[NSPECIES], cnt[NSPECIES], tiles[NSPECIES], qp[NSPECIES + 1];
    { int a = 0, q = 0;
      #pragma unroll
      for (int s = 0; s < NSPECIES; s++) {
          cnt[s] = g_meta[s];
          beg[s] = a; a += cnt[s];
          tiles[s] = (cnt[s] + TM - 1) / TM;
          qp[s] = q; q += (tiles[s] + NGROUPS - 1) / NGROUPS;
      }
      qp[NSPECIES] = q; }
    const int nquads = qp[NSPECIES];

    const int qpc = (nquads + gridDim.x - 1) / gridDim.x;
    const int q0 = blockIdx.x * qpc;
    const int q1 = min(q0 + qpc, nquads);

    int cur_s = -1;
    for (int q = q0; q < q1; q++) {
        int s = 3;
        if (q < qp[1]) s = 0; else if (q < qp[2]) s = 1; else if (q < qp[3]) s = 2;

        // ---- stage weights as bf16 hi/lo on species change ----
        if (s != cur_s) {
            __syncthreads();
            for (int i = tid; i < FDIM * HDIM; i += NTHREADS) {
                int k = i >> 6, j = i & 63;
                float w = W1[s * FDIM * HDIM + i];
                __nv_bfloat16 h = __float2bfloat16_rn(w);
                __nv_bfloat16 l = __float2bfloat16_rn(w - __bfloat162float(h));
                W1h[k * SA + j] = h;
                W1l[k * SA + j] = l;
            }
            for (int i = tid; i < HDIM * HDIM; i += NTHREADS) {
                int k = i >> 6, j = i & 63;
                float w = W2[s * HDIM * HDIM + i];
                __nv_bfloat16 h = __float2bfloat16_rn(w);
                __nv_bfloat16 l = __float2bfloat16_rn(w - __bfloat162float(h));
                W2h[k * SA + j] = h;
                W2l[k * SA + j] = l;
            }
            if (tid < HDIM) {
                b1f[tid] = b1[s * HDIM + tid];
                b2f[tid] = b2[s * HDIM + tid];
                w3f[tid] = W3[s * HDIM + tid];
            }
            if (tid == 0) b3f[0] = b3[s];
            cur_s = s;
            __syncthreads();
        }

        const int tile = (q - qp[s]) * NGROUPS + g;
        if (tile >= tiles[s]) continue;
        const int start = beg[s] + tile * TM;
        const int m = min(TM, cnt[s] - tile * TM);

        const int ridx = row < m ? row : m - 1;
        const int atom = g_sorted[start + ridx];
        const float* src = feats + (size_t)atom * FDIM + half * 32;

        wmma::fragment<wmma::accumulator, 16, 16, 16, float> acc[2][2];
        #pragma unroll
        for (int mm = 0; mm < 2; mm++)
            #pragma unroll
            for (int nn = 0; nn < 2; nn++) wmma::fill_fragment(acc[mm][nn], 0.0f);

        // ---- layer 1: two 64-k chunks (R12 gather: 8 independent LDG.128) ----
        #pragma unroll 1
        for (int c = 0; c < 2; c++) {
            {
                unsigned* hw = (unsigned*)(Bh + row * SA + half * 32);
                unsigned* lw = (unsigned*)(Bl + row * SA + half * 32);
                #pragma unroll
                for (int qq = 0; qq < 8; qq++) {
                    float4 v = *(const float4*)(src + c * 64 + qq * 4);
                    unsigned h0, l0, h1, l1;
                    split_pair(v.x, v.y, h0, l0);
                    split_pair(v.z, v.w, h1, l1);
                    hw[qq * 2] = h0; hw[qq * 2 + 1] = h1;
                    lw[qq * 2] = l0; lw[qq * 2 + 1] = l1;
                }
            }
            GBAR(barid);                           // A chunk visible

            #pragma unroll
            for (int ks = 0; ks < 4; ks++) {
                const int kg = c * 4 + ks;
                wmma::fragment<wmma::matrix_a, 16, 16, 16, __nv_bfloat16, wmma::row_major> ah[2], al[2];
                #pragma unroll
                for (int mm = 0; mm < 2; mm++) {
                    wmma::load_matrix_sync(ah[mm], Bh + (2 * wj + mm) * 16 * SA + ks * 16, SA);
                    wmma::load_matrix_sync(al[mm], Bl + (2 * wj + mm) * 16 * SA + ks * 16, SA);
                }
                #pragma unroll
                for (int nn = 0; nn < 2; nn++) {
                    wmma::fragment<wmma::matrix_b, 16, 16, 16, __nv_bfloat16, wmma::row_major> bh, bl;
                    wmma::load_matrix_sync(bh, W1h + kg * 16 * SA + (2 * wi + nn) * 16, SA);
                    wmma::load_matrix_sync(bl, W1l + kg * 16 * SA + (2 * wi + nn) * 16, SA);
                    #pragma unroll
                    for (int mm = 0; mm < 2; mm++) {
                        wmma::mma_sync(acc[mm][nn], ah[mm], bh, acc[mm][nn]);
                        wmma::mma_sync(acc[mm][nn], al[mm], bh, acc[mm][nn]);
                        wmma::mma_sync(acc[mm][nn], ah[mm], bl, acc[mm][nn]);
                    }
                }
            }
            if (c == 0) GBAR(barid);               // A reads done before c1 gather
        }

        // ---- O1 -> separate fp32 region (no alias with Bh/Bl) ----
        #pragma unroll
        for (int mm = 0; mm < 2; mm++)
            #pragma unroll
            for (int nn = 0; nn < 2; nn++)
                wmma::store_matrix_sync(Of + (2 * wj + mm) * 16 * SAO + (2 * wi + nn) * 16,
                                        acc[mm][nn], SAO, wmma::mem_row_major);
        GBAR(barid);   // O1 visible AND all c1 A-reads done (pre-store per warp)

        // ---- act1: tanh(+b1), split -> H into Bh/Bl (A-reads already fenced) ----
        {
            const float* orow = Of + row * SAO + half * 32;
            const float* bb = b1f + half * 32;
            unsigned* hw = (unsigned*)(Bh + row * SA + half * 32);
            unsigned* lw = (unsigned*)(Bl + row * SA + half * 32);
            #pragma unroll
            for (int p = 0; p < 16; p++) {
                float x = fast_tanh(orow[2 * p] + bb[2 * p]);
                float y = fast_tanh(orow[2 * p + 1] + bb[2 * p + 1]);
                unsigned h, l;
                split_pair(x, y, h, l);
                hw[p] = h; lw[p] = l;
            }
        }
        GBAR(barid);   // H visible

        // ---- layer 2: K = 64 ----
        #pragma unroll
        for (int mm = 0; mm < 2; mm++)
            #pragma unroll
            for (int nn = 0; nn < 2; nn++) wmma::fill_fragment(acc[mm][nn], 0.0f);
        #pragma unroll
        for (int ks = 0; ks < 4; ks++) {
            wmma::fragment<wmma::matrix_a, 16, 16, 16, __nv_bfloat16, wmma::row_major> ah[2], al[2];
            #pragma unroll
            for (int mm = 0; mm < 2; mm++) {
                wmma::load_matrix_sync(ah[mm], Bh + (2 * wj + mm) * 16 * SA + ks * 16, SA);
                wmma::load_matrix_sync(al[mm], Bl + (2 * wj + mm) * 16 * SA + ks * 16, SA);
            }
            #pragma unroll
            for (int nn = 0; nn < 2; nn++) {
                wmma::fragment<wmma::matrix_b, 16, 16, 16, __nv_bfloat16, wmma::row_major> bh, bl;
                wmma::load_matrix_sync(bh, W2h + ks * 16 * SA + (2 * wi + nn) * 16, SA);
                wmma::load_matrix_sync(bl, W2l + ks * 16 * SA + (2 * wi + nn) * 16, SA);
                #pragma unroll
                for (int mm = 0; mm < 2; mm++) {
                    wmma::mma_sync(acc[mm][nn], ah[mm], bh, acc[mm][nn]);
                    wmma::mma_sync(acc[mm][nn], al[mm], bh, acc[mm][nn]);
                    wmma::mma_sync(acc[mm][nn], ah[mm], bl, acc[mm][nn]);
                }
            }
        }

        // ---- O2 -> Of (O1 reads finished before the H-visible barrier) ----
        #pragma unroll
        for (int mm = 0; mm < 2; mm++)
            #pragma unroll
            for (int nn = 0; nn < 2; nn++)
                wmma::store_matrix_sync(Of + (2 * wj + mm) * 16 * SAO + (2 * wi + nn) * 16,
                                        acc[mm][nn], SAO, wmma::mem_row_major);
        GBAR(barid);   // O2 visible AND H reads done (pre-store per warp)

        // ---- epilogue: tanh(+b2) dot w3, combine halves ----
        {
            float e = 0.0f;
            const float* orow = Of + row * SAO + half * 32;
            const float* bb = b2f + half * 32;
            const float* ww = w3f + half * 32;
            #pragma unroll
            for (int i = 0; i < 32; i++)
                e += fast_tanh(orow[i] + bb[i]) * ww[i];
            if (half == 1) EP[row] = e;
            GBAR(barid);
            if (half == 0 && row < m)
                out[g_sorted[start + row]] = e + EP[row] + b3f[0];
        }
        // next tile's first gather barrier orders Bh/Bl reuse; Of reuse is
        // ordered by the O1-store barrier of the next tile.
    }
}

// ---------------- launch ----------------
extern "C" void kernel_launch(void* const* d_in, const int* in_sizes, int n_in,
                              void* d_out, int out_size)
{
    const float* feats   = (const float*)d_in[0];
    const void*  species = d_in[1];
    const float* W1 = (const float*)d_in[2];
    const float* b1 = (const float*)d_in[3];
    const float* W2 = (const float*)d_in[4];
    const float* b2 = (const float*)d_in[5];
    const float* W3 = (const float*)d_in[6];
    const float* b3 = (const float*)d_in[7];
    float* out = (float*)d_out;
    const int n = out_size;

    int dev = 0;
    cudaGetDevice(&dev);
    int nsm = 148;
    cudaDeviceGetAttribute(&nsm, cudaDevAttrMultiProcessorCount, dev);

    // launch order: init(1) hist(2) scatter(3) wmma(4) -> ncu captures #4
    init_kernel<<<1, 128>>>((const long long*)species, n);
    hist_kernel<<<nsm, 256>>>(species, n);
    scatter_kernel<<<nsm, 256>>>(species, n);

    cudaFuncSetAttribute(wmma_mlp_kernel,
                         cudaFuncAttributeMaxDynamicSharedMemorySize,
                         SMEM_BYTES);
    wmma_mlp_kernel<<<nsm, NTHREADS, SMEM_BYTES>>>(feats, W1, b1, W2, b2, W3, b3, out);
}

// round 15
// speedup vs baseline: 1.4040x; 1.4040x over previous
#include <cuda_runtime.h>
#include <cuda_bf16.h>
#include <mma.h>
#include <cstdint>

using namespace nvcuda;

#define NSPECIES 4
#define FDIM 128
#define HDIM 64
#define MAXN 2000000
#define TM 128                // atoms per tile (per group)
#define NGROUPS 2             // groups of 256 threads (8 warps)
#define GSIZE 256
#define NTHREADS 512
#define SA 72                 // stride (elements) for all tiles (R12-validated)

// ---------------- device scratch ----------------
__device__ int g_meta[8];     // [0..3] counts, [4..7] scatter cursors
__device__ int g_is64;
__device__ int g_sorted[MAXN];

// ---------------- helpers ----------------
__device__ __forceinline__ float fast_tanh(float x) {
    // tanh(x) = 1 - 2/(exp(2x)+1); stable at +/-inf.
    float e = __expf(2.0f * x);
    return 1.0f - __fdividef(2.0f, e + 1.0f);
}
__device__ __forceinline__ unsigned bf2pack(float flo, float fhi) {
    unsigned r;
    asm("cvt.rn.bf16x2.f32 %0, %1, %2;" : "=r"(r) : "f"(fhi), "f"(flo));
    return r;
}
__device__ __forceinline__ float2 bf2unpack(unsigned u) {
    __nv_bfloat162 h = *reinterpret_cast<__nv_bfloat162*>(&u);
    return __bfloat1622float2(h);
}
__device__ __forceinline__ void split_pair(float f0, float f1,
                                           unsigned& hi, unsigned& lo) {
    hi = bf2pack(f0, f1);
    float2 b = bf2unpack(hi);
    lo = bf2pack(f0 - b.x, f1 - b.y);
}

// ---------------- preproc (validated) ----------------
__global__ void init_kernel(const long long* __restrict__ sp, int n) {
    __shared__ int s_ok;
    if (threadIdx.x == 0) s_ok = 1;
    __syncthreads();
    const int m = (n / 2 < 128) ? n / 2 : 128;
    if (threadIdx.x < m) {
        long long v = sp[threadIdx.x];
        if (v < 0 || v > 3) atomicExch(&s_ok, 0);
    }
    __syncthreads();
    if (threadIdx.x == 0) g_is64 = s_ok;
    if (threadIdx.x < 8) g_meta[threadIdx.x] = 0;
}
__device__ __forceinline__ int load_sp(const void* sp, int i, int is64) {
    return is64 ? (int)((const long long*)sp)[i] : ((const int*)sp)[i];
}
__global__ void hist_kernel(const void* __restrict__ sp, int n) {
    __shared__ int hs[NSPECIES];
    if (threadIdx.x < NSPECIES) hs[threadIdx.x] = 0;
    __syncthreads();
    const int is64 = g_is64;
    const int stride = gridDim.x * blockDim.x;
    for (int i = blockIdx.x * blockDim.x + threadIdx.x; i < n; i += stride)
        atomicAdd(&hs[load_sp(sp, i, is64)], 1);
    __syncthreads();
    if (threadIdx.x < NSPECIES) atomicAdd(&g_meta[threadIdx.x], hs[threadIdx.x]);
}
__global__ void scatter_kernel(const void* __restrict__ sp, int n) {
    const int is64 = g_is64;
    int offs[NSPECIES];
    { int a = 0;
      #pragma unroll
      for (int s = 0; s < NSPECIES; s++) { offs[s] = a; a += g_meta[s]; } }
    const int stride = gridDim.x * blockDim.x;
    const int lane = threadIdx.x & 31;
    for (int i = blockIdx.x * blockDim.x + threadIdx.x; i < n; i += stride) {
        int s = load_sp(sp, i, is64);
        unsigned act = __activemask();
        unsigned peers = __match_any_sync(act, s);
        int leader = __ffs(peers) - 1;
        int cnt = __popc(peers);
        int base = 0;
        if (lane == leader) base = atomicAdd(&g_meta[NSPECIES + s], cnt);
        base = __shfl_sync(peers, base, leader);
        g_sorted[offs[s] + base + __popc(peers & ((1u << lane) - 1u))] = i;
    }
}

// ---------------- SMEM byte layout (totals identical to R12) ----------------
#define BY_W1H 0
#define BY_W1L (BY_W1H + FDIM * SA * 2)            // 18432
#define BY_W2H (BY_W1L + FDIM * SA * 2)            // 36864
#define BY_W2L (BY_W2H + HDIM * SA * 2)            // 46080
#define BY_BUF (BY_W2L + HDIM * SA * 2)            // 55296; per group TM*SA*4 B
#define BY_B1  (BY_BUF + NGROUPS * TM * SA * 4)    // 129024
#define BY_B2  (BY_B1 + HDIM * 4)
#define BY_W3  (BY_B2 + HDIM * 4)
#define BY_B3  (BY_W3 + HDIM * 4)                  // 129792
#define BY_EP  (BY_B3 + 16)                        // 129808
#define SMEM_BYTES (BY_EP + NGROUPS * TM * 4)      // 130832

extern __shared__ char smc[];

#define GBAR(id) asm volatile("bar.sync %0, %1;" :: "r"(id), "n"(GSIZE) : "memory")

__global__ void __launch_bounds__(NTHREADS, 1)
wmma_mlp_kernel(const float* __restrict__ feats,
                const float* __restrict__ W1, const float* __restrict__ b1,
                const float* __restrict__ W2, const float* __restrict__ b2,
                const float* __restrict__ W3, const float* __restrict__ b3,
                float* __restrict__ out)
{
    const int tid  = threadIdx.x;
    const int g    = tid >> 8;            // group 0..1
    const int gid  = tid & 255;
    const int wg   = gid >> 5;            // warp in group 0..7
    const int wj   = wg >> 1;             // M-pair 0..3 (M-tiles 2wj, 2wj+1)
    const int wi   = wg & 1;              // N-pair 0..1 (N-tiles 2wi, 2wi+1)
    const int row  = gid & 127;           // atom row for scalar passes
    const int half = gid >> 7;            // column half 0/1
    const int barid = 1 + g;

    __nv_bfloat16* W1h = (__nv_bfloat16*)(smc + BY_W1H);
    __nv_bfloat16* W1l = (__nv_bfloat16*)(smc + BY_W1L);
    __nv_bfloat16* W2h = (__nv_bfloat16*)(smc + BY_W2H);
    __nv_bfloat16* W2l = (__nv_bfloat16*)(smc + BY_W2L);
    char* BUF = smc + BY_BUF + g * TM * SA * 4;
    __nv_bfloat16* Bh = (__nv_bfloat16*)BUF;          // [128][SA] bf16
    __nv_bfloat16* Bl = Bh + TM * SA;                  // [128][SA] bf16
    float* Of = (float*)BUF;                           // [128][SA] fp32 (aliases)
    float* b1f = (float*)(smc + BY_B1);
    float* b2f = (float*)(smc + BY_B2);
    float* w3f = (float*)(smc + BY_W3);
    float* b3f = (float*)(smc + BY_B3);
    float* EP  = (float*)(smc + BY_EP) + g * TM;

    // ---- species / tile / pair tables ----
    int beg[NSPECIES], cnt[NSPECIES], tiles[NSPECIES], qp[NSPECIES + 1];
    { int a = 0, q = 0;
      #pragma unroll
      for (int s = 0; s < NSPECIES; s++) {
          cnt[s] = g_meta[s];
          beg[s] = a; a += cnt[s];
          tiles[s] = (cnt[s] + TM - 1) / TM;
          qp[s] = q; q += (tiles[s] + NGROUPS - 1) / NGROUPS;
      }
      qp[NSPECIES] = q; }
    const int nquads = qp[NSPECIES];

    const int qpc = (nquads + gridDim.x - 1) / gridDim.x;
    const int q0 = blockIdx.x * qpc;
    const int q1 = min(q0 + qpc, nquads);

    int cur_s = -1;
    for (int q = q0; q < q1; q++) {
        int s = 3;
        if (q < qp[1]) s = 0; else if (q < qp[2]) s = 1; else if (q < qp[3]) s = 2;

        // ---- stage weights as bf16 hi/lo on species change ----
        if (s != cur_s) {
            __syncthreads();
            for (int i = tid; i < FDIM * HDIM; i += NTHREADS) {
                int k = i >> 6, j = i & 63;
                float w = W1[s * FDIM * HDIM + i];
                __nv_bfloat16 h = __float2bfloat16_rn(w);
                __nv_bfloat16 l = __float2bfloat16_rn(w - __bfloat162float(h));
                W1h[k * SA + j] = h;
                W1l[k * SA + j] = l;
            }
            for (int i = tid; i < HDIM * HDIM; i += NTHREADS) {
                int k = i >> 6, j = i & 63;
                float w = W2[s * HDIM * HDIM + i];
                __nv_bfloat16 h = __float2bfloat16_rn(w);
                __nv_bfloat16 l = __float2bfloat16_rn(w - __bfloat162float(h));
                W2h[k * SA + j] = h;
                W2l[k * SA + j] = l;
            }
            if (tid < HDIM) {
                b1f[tid] = b1[s * HDIM + tid];
                b2f[tid] = b2[s * HDIM + tid];
                w3f[tid] = W3[s * HDIM + tid];
            }
            if (tid == 0) b3f[0] = b3[s];
            cur_s = s;
            __syncthreads();
        }

        const int tile = (q - qp[s]) * NGROUPS + g;
        if (tile >= tiles[s]) continue;
        const int start = beg[s] + tile * TM;
        const int m = min(TM, cnt[s] - tile * TM);

        const int ridx = row < m ? row : m - 1;
        const int atom = g_sorted[start + ridx];
        const float* src = feats + (size_t)atom * FDIM + half * 32;

        wmma::fragment<wmma::accumulator, 16, 16, 16, float> acc[2][2];
        #pragma unroll
        for (int mm = 0; mm < 2; mm++)
            #pragma unroll
            for (int nn = 0; nn < 2; nn++) wmma::fill_fragment(acc[mm][nn], 0.0f);

        // ---- layer 1: two 64-k chunks (R12 gather: 8 independent LDG.128) ----
        #pragma unroll 1
        for (int c = 0; c < 2; c++) {
            {
                unsigned* hw = (unsigned*)(Bh + row * SA + half * 32);
                unsigned* lw = (unsigned*)(Bl + row * SA + half * 32);
                #pragma unroll
                for (int qq = 0; qq < 8; qq++) {
                    float4 v = *(const float4*)(src + c * 64 + qq * 4);
                    unsigned h0, l0, h1, l1;
                    split_pair(v.x, v.y, h0, l0);
                    split_pair(v.z, v.w, h1, l1);
                    hw[qq * 2] = h0; hw[qq * 2 + 1] = h1;
                    lw[qq * 2] = l0; lw[qq * 2 + 1] = l1;
                }
            }
            GBAR(barid);

            #pragma unroll
            for (int ks = 0; ks < 4; ks++) {
                const int kg = c * 4 + ks;
                wmma::fragment<wmma::matrix_a, 16, 16, 16, __nv_bfloat16, wmma::row_major> ah[2], al[2];
                #pragma unroll
                for (int mm = 0; mm < 2; mm++) {
                    wmma::load_matrix_sync(ah[mm], Bh + (2 * wj + mm) * 16 * SA + ks * 16, SA);
                    wmma::load_matrix_sync(al[mm], Bl + (2 * wj + mm) * 16 * SA + ks * 16, SA);
                }
                #pragma unroll
                for (int nn = 0; nn < 2; nn++) {
                    wmma::fragment<wmma::matrix_b, 16, 16, 16, __nv_bfloat16, wmma::row_major> bh, bl;
                    wmma::load_matrix_sync(bh, W1h + kg * 16 * SA + (2 * wi + nn) * 16, SA);
                    wmma::load_matrix_sync(bl, W1l + kg * 16 * SA + (2 * wi + nn) * 16, SA);
                    #pragma unroll
                    for (int mm = 0; mm < 2; mm++) {
                        wmma::mma_sync(acc[mm][nn], ah[mm], bh, acc[mm][nn]);
                        wmma::mma_sync(acc[mm][nn], al[mm], bh, acc[mm][nn]);
                        wmma::mma_sync(acc[mm][nn], ah[mm], bl, acc[mm][nn]);
                    }
                }
            }
            GBAR(barid);   // all warps' A loads done before BUF overwrite
        }

        // ---- O1 = acc -> smem (fp32, stride SA, aliases BUF) ----
        #pragma unroll
        for (int mm = 0; mm < 2; mm++)
            #pragma unroll
            for (int nn = 0; nn < 2; nn++)
                wmma::store_matrix_sync(Of + (2 * wj + mm) * 16 * SA + (2 * wi + nn) * 16,
                                        acc[mm][nn], SA, wmma::mem_row_major);
        GBAR(barid);

        // ---- act1: tanh(+b1) register-staged, split -> H in Bh/Bl ----
        {
            float vv[32];
            const float* orow = Of + row * SA + half * 32;
            const float* bb = b1f + half * 32;
            #pragma unroll
            for (int i = 0; i < 32; i++) vv[i] = fast_tanh(orow[i] + bb[i]);
            GBAR(barid);   // all O1 reads done before overwrite
            unsigned* hw = (unsigned*)(Bh + row * SA + half * 32);
            unsigned* lw = (unsigned*)(Bl + row * SA + half * 32);
            #pragma unroll
            for (int p = 0; p < 16; p++) {
                unsigned h, l;
                split_pair(vv[2 * p], vv[2 * p + 1], h, l);
                hw[p] = h; lw[p] = l;
            }
        }
        GBAR(barid);

        // ---- layer 2: K = 64 ----
        #pragma unroll
        for (int mm = 0; mm < 2; mm++)
            #pragma unroll
            for (int nn = 0; nn < 2; nn++) wmma::fill_fragment(acc[mm][nn], 0.0f);
        #pragma unroll
        for (int ks = 0; ks < 4; ks++) {
            wmma::fragment<wmma::matrix_a, 16, 16, 16, __nv_bfloat16, wmma::row_major> ah[2], al[2];
            #pragma unroll
            for (int mm = 0; mm < 2; mm++) {
                wmma::load_matrix_sync(ah[mm], Bh + (2 * wj + mm) * 16 * SA + ks * 16, SA);
                wmma::load_matrix_sync(al[mm], Bl + (2 * wj + mm) * 16 * SA + ks * 16, SA);
            }
            #pragma unroll
            for (int nn = 0; nn < 2; nn++) {
                wmma::fragment<wmma::matrix_b, 16, 16, 16, __nv_bfloat16, wmma::row_major> bh, bl;
                wmma::load_matrix_sync(bh, W2h + ks * 16 * SA + (2 * wi + nn) * 16, SA);
                wmma::load_matrix_sync(bl, W2l + ks * 16 * SA + (2 * wi + nn) * 16, SA);
                #pragma unroll
                for (int mm = 0; mm < 2; mm++) {
                    wmma::mma_sync(acc[mm][nn], ah[mm], bh, acc[mm][nn]);
                    wmma::mma_sync(acc[mm][nn], al[mm], bh, acc[mm][nn]);
                    wmma::mma_sync(acc[mm][nn], ah[mm], bl, acc[mm][nn]);
                }
            }
        }
        GBAR(barid);   // all H reads done before O2 overwrite

        #pragma unroll
        for (int mm = 0; mm < 2; mm++)
            #pragma unroll
            for (int nn = 0; nn < 2; nn++)
                wmma::store_matrix_sync(Of + (2 * wj + mm) * 16 * SA + (2 * wi + nn) * 16,
                                        acc[mm][nn], SA, wmma::mem_row_major);
        GBAR(barid);

        // ---- epilogue: tanh(+b2) dot w3, combine halves ----
        {
            float e = 0.0f;
            const float* orow = Of + row * SA + half * 32;
            const float* bb = b2f + half * 32;
            const float* ww = w3f + half * 32;
            #pragma unroll
            for (int i = 0; i < 32; i++)
                e += fast_tanh(orow[i] + bb[i]) * ww[i];
            if (half == 1) EP[row] = e;
            GBAR(barid);
            if (half == 0 && row < m)
                out[g_sorted[start + row]] = e + EP[row] + b3f[0];
        }
        // next-iteration BUF writes are ordered by the next gather GBAR
    }
}

// ---------------- launch ----------------
extern "C" void kernel_launch(void* const* d_in, const int* in_sizes, int n_in,
                              void* d_out, int out_size)
{
    const float* feats   = (const float*)d_in[0];
    const void*  species = d_in[1];
    const float* W1 = (const float*)d_in[2];
    const float* b1 = (const float*)d_in[3];
    const float* W2 = (const float*)d_in[4];
    const float* b2 = (const float*)d_in[5];
    const float* W3 = (const float*)d_in[6];
    const float* b3 = (const float*)d_in[7];
    float* out = (float*)d_out;
    const int n = out_size;

    int dev = 0;
    cudaGetDevice(&dev);
    int nsm = 148;
    cudaDeviceGetAttribute(&nsm, cudaDevAttrMultiProcessorCount, dev);

    // launch order: init(1) hist(2) scatter(3) wmma(4) -> ncu captures #4
    init_kernel<<<1, 128>>>((const long long*)species, n);
    hist_kernel<<<nsm, 256>>>(species, n);
    scatter_kernel<<<nsm, 256>>>(species, n);

    cudaFuncSetAttribute(wmma_mlp_kernel,
                         cudaFuncAttributeMaxDynamicSharedMemorySize,
                         SMEM_BYTES);
    wmma_mlp_kernel<<<nsm, NTHREADS, SMEM_BYTES>>>(feats, W1, b1, W2, b2, W3, b3, out);
}

// round 16
// speedup vs baseline: 2.2449x; 1.5990x over previous
#include <cuda_runtime.h>
#include <cuda_fp16.h>
#include <mma.h>
#include <cstdint>

using namespace nvcuda;

#define NSPECIES 4
#define FDIM 128
#define HDIM 64
#define MAXN 2000000
#define TM 64                 // atoms per tile (per group)
#define NGROUPS 4
#define NTHREADS 512
#define SA 72                 // tile stride (elements): ldmatrix conflict-free

// ---------------- device scratch ----------------
__device__ int g_meta[8];     // [0..3] counts, [4..7] scatter cursors
__device__ int g_is64;
__device__ int g_sorted[MAXN];

// ---------------- helpers ----------------
__device__ __forceinline__ float fast_tanh(float x) {
    // tanh(x) = 1 - 2/(exp(2x)+1); stable at +/-inf.
    float e = __expf(2.0f * x);
    return 1.0f - __fdividef(2.0f, e + 1.0f);
}
__device__ __forceinline__ unsigned h2pack(float f0, float f1) {
    __half2 h = __floats2half2_rn(f0, f1);
    return *reinterpret_cast<unsigned*>(&h);
}

// ---------------- preproc (validated) ----------------
__global__ void init_kernel(const long long* __restrict__ sp, int n) {
    __shared__ int s_ok;
    if (threadIdx.x == 0) s_ok = 1;
    __syncthreads();
    const int m = (n / 2 < 128) ? n / 2 : 128;
    if (threadIdx.x < m) {
        long long v = sp[threadIdx.x];
        if (v < 0 || v > 3) atomicExch(&s_ok, 0);
    }
    __syncthreads();
    if (threadIdx.x == 0) g_is64 = s_ok;
    if (threadIdx.x < 8) g_meta[threadIdx.x] = 0;
}
__device__ __forceinline__ int load_sp(const void* sp, int i, int is64) {
    return is64 ? (int)((const long long*)sp)[i] : ((const int*)sp)[i];
}
__global__ void hist_kernel(const void* __restrict__ sp, int n) {
    __shared__ int hs[NSPECIES];
    if (threadIdx.x < NSPECIES) hs[threadIdx.x] = 0;
    __syncthreads();
    const int is64 = g_is64;
    const int stride = gridDim.x * blockDim.x;
    for (int i = blockIdx.x * blockDim.x + threadIdx.x; i < n; i += stride)
        atomicAdd(&hs[load_sp(sp, i, is64)], 1);
    __syncthreads();
    if (threadIdx.x < NSPECIES) atomicAdd(&g_meta[threadIdx.x], hs[threadIdx.x]);
}
__global__ void scatter_kernel(const void* __restrict__ sp, int n) {
    const int is64 = g_is64;
    int offs[NSPECIES];
    { int a = 0;
      #pragma unroll
      for (int s = 0; s < NSPECIES; s++) { offs[s] = a; a += g_meta[s]; } }
    const int stride = gridDim.x * blockDim.x;
    const int lane = threadIdx.x & 31;
    for (int i = blockIdx.x * blockDim.x + threadIdx.x; i < n; i += stride) {
        int s = load_sp(sp, i, is64);
        unsigned act = __activemask();
        unsigned peers = __match_any_sync(act, s);
        int leader = __ffs(peers) - 1;
        int cnt = __popc(peers);
        int base = 0;
        if (lane == leader) base = atomicAdd(&g_meta[NSPECIES + s], cnt);
        base = __shfl_sync(peers, base, leader);
        g_sorted[offs[s] + base + __popc(peers & ((1u << lane) - 1u))] = i;
    }
}

// ---------------- SMEM byte layout ----------------
#define BY_W1  0                                   // fp16 [128][SA] = 18432
#define BY_W2  (BY_W1 + FDIM * SA * 2)             // fp16 [64][SA]  = 9216
#define BY_BUF (BY_W2 + HDIM * SA * 2)             // 27648; per group TM*SA*4 B
#define BY_B1  (BY_BUF + NGROUPS * TM * SA * 4)    // 101376
#define BY_B2  (BY_B1 + HDIM * 4)
#define BY_W3  (BY_B2 + HDIM * 4)
#define BY_B3  (BY_W3 + HDIM * 4)                  // 102144
#define BY_EP  (BY_B3 + 16)                        // 102160
#define SMEM_BYTES (BY_EP + NGROUPS * TM * 4)      // 103184

extern __shared__ char smc[];

#define GBAR(id) asm volatile("bar.sync %0, 128;" :: "r"(id) : "memory")

__global__ void __launch_bounds__(NTHREADS, 1)
wmma_mlp_kernel(const float* __restrict__ feats,
                const float* __restrict__ W1, const float* __restrict__ b1,
                const float* __restrict__ W2, const float* __restrict__ b2,
                const float* __restrict__ W3, const float* __restrict__ b3,
                float* __restrict__ out)
{
    const int tid  = threadIdx.x;
    const int g    = tid >> 7;            // group 0..3
    const int gid  = tid & 127;
    const int wg   = gid >> 5;            // warp in group 0..3
    const int wj   = wg >> 1;             // M-half (2 tiles)
    const int wi   = wg & 1;              // N-half (2 tiles)
    const int row  = gid & 63;            // atom row for scalar passes
    const int half = gid >> 6;            // column half 0/1
    const int barid = 1 + g;

    __half* W1h = (__half*)(smc + BY_W1);
    __half* W2h = (__half*)(smc + BY_W2);
    char* BUF = smc + BY_BUF + g * TM * SA * 4;    // 18432 B per group
    __half* Bh = (__half*)BUF;                     // [64][SA] fp16 (first 9216 B)
    float* Of  = (float*)BUF;                      // [64][SA] fp32 (aliases, full)
    float* b1f = (float*)(smc + BY_B1);
    float* b2f = (float*)(smc + BY_B2);
    float* w3f = (float*)(smc + BY_W3);
    float* b3f = (float*)(smc + BY_B3);
    float* EP  = (float*)(smc + BY_EP) + g * TM;

    // ---- species / tile / quad tables ----
    int beg[NSPECIES], cnt[NSPECIES], tiles[NSPECIES], qp[NSPECIES + 1];
    { int a = 0, q = 0;
      #pragma unroll
      for (int s = 0; s < NSPECIES; s++) {
          cnt[s] = g_meta[s];
          beg[s] = a; a += cnt[s];
          tiles[s] = (cnt[s] + TM - 1) / TM;
          qp[s] = q; q += (tiles[s] + NGROUPS - 1) / NGROUPS;
      }
      qp[NSPECIES] = q; }
    const int nquads = qp[NSPECIES];

    const int qpc = (nquads + gridDim.x - 1) / gridDim.x;
    const int q0 = blockIdx.x * qpc;
    const int q1 = min(q0 + qpc, nquads);

    int cur_s = -1;
    for (int q = q0; q < q1; q++) {
        int s = 3;
        if (q < qp[1]) s = 0; else if (q < qp[2]) s = 1; else if (q < qp[3]) s = 2;

        // ---- stage weights as fp16 on species change ----
        if (s != cur_s) {
            __syncthreads();
            for (int i = tid; i < FDIM * HDIM; i += NTHREADS) {
                int k = i >> 6, j = i & 63;
                W1h[k * SA + j] = __float2half_rn(W1[s * FDIM * HDIM + i]);
            }
            for (int i = tid; i < HDIM * HDIM; i += NTHREADS) {
                int k = i >> 6, j = i & 63;
                W2h[k * SA + j] = __float2half_rn(W2[s * HDIM * HDIM + i]);
            }
            if (tid < HDIM) {
                b1f[tid] = b1[s * HDIM + tid];
                b2f[tid] = b2[s * HDIM + tid];
                w3f[tid] = W3[s * HDIM + tid];
            }
            if (tid == 0) b3f[0] = b3[s];
            cur_s = s;
            __syncthreads();
        }

        const int tile = (q - qp[s]) * NGROUPS + g;
        if (tile >= tiles[s]) continue;
        const int start = beg[s] + tile * TM;
        const int m = min(TM, cnt[s] - tile * TM);

        const int ridx = row < m ? row : m - 1;
        const int atom = g_sorted[start + ridx];
        const float* src = feats + (size_t)atom * FDIM + half * 32;

        wmma::fragment<wmma::accumulator, 16, 16, 16, float> acc[2][2];
        #pragma unroll
        for (int mm = 0; mm < 2; mm++)
            #pragma unroll
            for (int nn = 0; nn < 2; nn++) wmma::fill_fragment(acc[mm][nn], 0.0f);

        // ---- layer 1: two 64-k chunks (R12 gather: 8 independent LDG.128) ----
        #pragma unroll 1
        for (int c = 0; c < 2; c++) {
            {
                unsigned* hw = (unsigned*)(Bh + row * SA + half * 32);
                #pragma unroll
                for (int qq = 0; qq < 8; qq++) {
                    float4 v = *(const float4*)(src + c * 64 + qq * 4);
                    hw[qq * 2]     = h2pack(v.x, v.y);
                    hw[qq * 2 + 1] = h2pack(v.z, v.w);
                }
            }
            GBAR(barid);                           // A chunk visible

            #pragma unroll
            for (int ks = 0; ks < 4; ks++) {
                const int kg = c * 4 + ks;
                wmma::fragment<wmma::matrix_a, 16, 16, 16, __half, wmma::row_major> a[2];
                #pragma unroll
                for (int mm = 0; mm < 2; mm++)
                    wmma::load_matrix_sync(a[mm], Bh + (2 * wj + mm) * 16 * SA + ks * 16, SA);
                #pragma unroll
                for (int nn = 0; nn < 2; nn++) {
                    wmma::fragment<wmma::matrix_b, 16, 16, 16, __half, wmma::row_major> b;
                    wmma::load_matrix_sync(b, W1h + kg * 16 * SA + (2 * wi + nn) * 16, SA);
                    #pragma unroll
                    for (int mm = 0; mm < 2; mm++)
                        wmma::mma_sync(acc[mm][nn], a[mm], b, acc[mm][nn]);
                }
            }
            GBAR(barid);   // all warps' A loads done before BUF overwrite
        }

        // ---- O1 = acc -> smem (fp32, stride SA, aliases BUF) ----
        #pragma unroll
        for (int mm = 0; mm < 2; mm++)
            #pragma unroll
            for (int nn = 0; nn < 2; nn++)
                wmma::store_matrix_sync(Of + (2 * wj + mm) * 16 * SA + (2 * wi + nn) * 16,
                                        acc[mm][nn], SA, wmma::mem_row_major);
        GBAR(barid);

        // ---- act1: tanh(+b1) register-staged, cvt fp16 -> H in Bh ----
        {
            float vv[32];
            const float* orow = Of + row * SA + half * 32;
            const float* bb = b1f + half * 32;
            #pragma unroll
            for (int i = 0; i < 32; i++) vv[i] = fast_tanh(orow[i] + bb[i]);
            GBAR(barid);   // all O1 reads done before overwrite
            unsigned* hw = (unsigned*)(Bh + row * SA + half * 32);
            #pragma unroll
            for (int p = 0; p < 16; p++)
                hw[p] = h2pack(vv[2 * p], vv[2 * p + 1]);
        }
        GBAR(barid);

        // ---- layer 2: K = 64 ----
        #pragma unroll
        for (int mm = 0; mm < 2; mm++)
            #pragma unroll
            for (int nn = 0; nn < 2; nn++) wmma::fill_fragment(acc[mm][nn], 0.0f);
        #pragma unroll
        for (int ks = 0; ks < 4; ks++) {
            wmma::fragment<wmma::matrix_a, 16, 16, 16, __half, wmma::row_major> a[2];
            #pragma unroll
            for (int mm = 0; mm < 2; mm++)
                wmma::load_matrix_sync(a[mm], Bh + (2 * wj + mm) * 16 * SA + ks * 16, SA);
            #pragma unroll
            for (int nn = 0; nn < 2; nn++) {
                wmma::fragment<wmma::matrix_b, 16, 16, 16, __half, wmma::row_major> b;
                wmma::load_matrix_sync(b, W2h + ks * 16 * SA + (2 * wi + nn) * 16, SA);
                #pragma unroll
                for (int mm = 0; mm < 2; mm++)
                    wmma::mma_sync(acc[mm][nn], a[mm], b, acc[mm][nn]);
            }
        }
        GBAR(barid);   // all H reads done before O2 overwrite

        #pragma unroll
        for (int mm = 0; mm < 2; mm++)
            #pragma unroll
            for (int nn = 0; nn < 2; nn++)
                wmma::store_matrix_sync(Of + (2 * wj + mm) * 16 * SA + (2 * wi + nn) * 16,
                                        acc[mm][nn], SA, wmma::mem_row_major);
        GBAR(barid);

        // ---- epilogue: tanh(+b2) dot w3, combine halves ----
        {
            float e = 0.0f;
            const float* orow = Of + row * SA + half * 32;
            const float* bb = b2f + half * 32;
            const float* ww = w3f + half * 32;
            #pragma unroll
            for (int i = 0; i < 32; i++)
                e += fast_tanh(orow[i] + bb[i]) * ww[i];
            if (half == 1) EP[row] = e;
            GBAR(barid);
            if (half == 0 && row < m)
                out[g_sorted[start + row]] = e + EP[row] + b3f[0];
        }
        // next-iteration BUF writes are ordered by the next gather GBAR
    }
}

// ---------------- launch ----------------
extern "C" void kernel_launch(void* const* d_in, const int* in_sizes, int n_in,
                              void* d_out, int out_size)
{
    const float* feats   = (const float*)d_in[0];
    const void*  species = d_in[1];
    const float* W1 = (const float*)d_in[2];
    const float* b1 = (const float*)d_in[3];
    const float* W2 = (const float*)d_in[4];
    const float* b2 = (const float*)d_in[5];
    const float* W3 = (const float*)d_in[6];
    const float* b3 = (const float*)d_in[7];
    float* out = (float*)d_out;
    const int n = out_size;

    int dev = 0;
    cudaGetDevice(&dev);
    int nsm = 148;
    cudaDeviceGetAttribute(&nsm, cudaDevAttrMultiProcessorCount, dev);

    // launch order: init(1) hist(2) scatter(3) wmma(4) -> ncu captures #4
    init_kernel<<<1, 128>>>((const long long*)species, n);
    hist_kernel<<<nsm, 256>>>(species, n);
    scatter_kernel<<<nsm, 256>>>(species, n);

    cudaFuncSetAttribute(wmma_mlp_kernel,
                         cudaFuncAttributeMaxDynamicSharedMemorySize,
                         SMEM_BYTES);
    wmma_mlp_kernel<<<nsm, NTHREADS, SMEM_BYTES>>>(feats, W1, b1, W2, b2, W3, b3, out);
}

// round 17
// speedup vs baseline: 2.9401x; 1.3097x over previous
#include <cuda_runtime.h>
#include <cuda_fp16.h>
#include <mma.h>
#include <cstdint>

using namespace nvcuda;

#define NSPECIES 4
#define FDIM 128
#define HDIM 64
#define MAXN 2000000
#define TM 64                 // atoms per tile (per group)
#define NGROUPS 4
#define NTHREADS 512
#define SA 72                 // tile stride (elements): ldmatrix conflict-free

// ---------------- device scratch ----------------
__device__ int g_meta[8];     // [0..3] counts, [4..7] scatter cursors
__device__ int g_is64;
__device__ int g_sorted[MAXN];

// ---------------- helpers ----------------
__device__ __forceinline__ float fast_tanh(float x) {
    // tanh(x) = 1 - 2/(exp(2x)+1); stable at +/-inf.
    float e = __expf(2.0f * x);
    return 1.0f - __fdividef(2.0f, e + 1.0f);
}
__device__ __forceinline__ unsigned h2pack(float f0, float f1) {
    __half2 h = __floats2half2_rn(f0, f1);
    return *reinterpret_cast<unsigned*>(&h);
}

// ---------------- preproc (validated) ----------------
__global__ void init_kernel(const long long* __restrict__ sp, int n) {
    __shared__ int s_ok;
    if (threadIdx.x == 0) s_ok = 1;
    __syncthreads();
    const int m = (n / 2 < 128) ? n / 2 : 128;
    if (threadIdx.x < m) {
        long long v = sp[threadIdx.x];
        if (v < 0 || v > 3) atomicExch(&s_ok, 0);
    }
    __syncthreads();
    if (threadIdx.x == 0) g_is64 = s_ok;
    if (threadIdx.x < 8) g_meta[threadIdx.x] = 0;
}
__device__ __forceinline__ int load_sp(const void* sp, int i, int is64) {
    return is64 ? (int)((const long long*)sp)[i] : ((const int*)sp)[i];
}
__global__ void hist_kernel(const void* __restrict__ sp, int n) {
    __shared__ int hs[NSPECIES];
    if (threadIdx.x < NSPECIES) hs[threadIdx.x] = 0;
    __syncthreads();
    const int is64 = g_is64;
    const int stride = gridDim.x * blockDim.x;
    for (int i = blockIdx.x * blockDim.x + threadIdx.x; i < n; i += stride)
        atomicAdd(&hs[load_sp(sp, i, is64)], 1);
    __syncthreads();
    if (threadIdx.x < NSPECIES) atomicAdd(&g_meta[threadIdx.x], hs[threadIdx.x]);
}
__global__ void scatter_kernel(const void* __restrict__ sp, int n) {
    const int is64 = g_is64;
    int offs[NSPECIES];
    { int a = 0;
      #pragma unroll
      for (int s = 0; s < NSPECIES; s++) { offs[s] = a; a += g_meta[s]; } }
    const int stride = gridDim.x * blockDim.x;
    const int lane = threadIdx.x & 31;
    for (int i = blockIdx.x * blockDim.x + threadIdx.x; i < n; i += stride) {
        int s = load_sp(sp, i, is64);
        unsigned act = __activemask();
        unsigned peers = __match_any_sync(act, s);
        int leader = __ffs(peers) - 1;
        int cnt = __popc(peers);
        int base = 0;
        if (lane == leader) base = atomicAdd(&g_meta[NSPECIES + s], cnt);
        base = __shfl_sync(peers, base, leader);
        g_sorted[offs[s] + base + __popc(peers & ((1u << lane) - 1u))] = i;
    }
}

// ---------------- SMEM byte layout (identical to R16) ----------------
#define BY_W1  0                                   // fp16 [128][SA] = 18432
#define BY_W2  (BY_W1 + FDIM * SA * 2)             // fp16 [64][SA]  = 9216
#define BY_BUF (BY_W2 + HDIM * SA * 2)             // 27648; per group TM*SA*4 B
#define BY_B1  (BY_BUF + NGROUPS * TM * SA * 4)    // 101376
#define BY_B2  (BY_B1 + HDIM * 4)
#define BY_W3  (BY_B2 + HDIM * 4)
#define BY_B3  (BY_W3 + HDIM * 4)                  // 102144
#define BY_EP  (BY_B3 + 16)                        // 102160
#define SMEM_BYTES (BY_EP + NGROUPS * TM * 4)      // 103184

extern __shared__ char smc[];

#define GBAR(id) asm volatile("bar.sync %0, 128;" :: "r"(id) : "memory")

__global__ void __launch_bounds__(NTHREADS, 1)
wmma_mlp_kernel(const float* __restrict__ feats,
                const float* __restrict__ W1, const float* __restrict__ b1,
                const float* __restrict__ W2, const float* __restrict__ b2,
                const float* __restrict__ W3, const float* __restrict__ b3,
                float* __restrict__ out)
{
    const int tid  = threadIdx.x;
    const int g    = tid >> 7;            // group 0..3
    const int gid  = tid & 127;
    const int wg   = gid >> 5;            // warp in group 0..3
    const int lane = gid & 31;
    const int wj   = wg >> 1;             // M-half (2 tiles)
    const int wi   = wg & 1;              // N-half (2 tiles)
    const int row  = gid & 63;            // atom row for scalar passes
    const int half = gid >> 6;            // column half 0/1
    const int aoff = lane >> 3;           // gather: atom sub-index 0..3
    const int foff = lane & 7;            // gather: float4 index 0..7
    const int barid = 1 + g;

    __half* W1h = (__half*)(smc + BY_W1);
    __half* W2h = (__half*)(smc + BY_W2);
    char* BUF = smc + BY_BUF + g * TM * SA * 4;    // 18432 B per group
    __half* Bh = (__half*)BUF;                     // [64][SA] fp16 (first 9216 B)
    float* Of  = (float*)BUF;                      // [64][SA] fp32 (aliases, full)
    float* b1f = (float*)(smc + BY_B1);
    float* b2f = (float*)(smc + BY_B2);
    float* w3f = (float*)(smc + BY_W3);
    float* b3f = (float*)(smc + BY_B3);
    float* EP  = (float*)(smc + BY_EP) + g * TM;

    // ---- species / tile / quad tables ----
    int beg[NSPECIES], cnt[NSPECIES], tiles[NSPECIES], qp[NSPECIES + 1];
    { int a = 0, q = 0;
      #pragma unroll
      for (int s = 0; s < NSPECIES; s++) {
          cnt[s] = g_meta[s];
          beg[s] = a; a += cnt[s];
          tiles[s] = (cnt[s] + TM - 1) / TM;
          qp[s] = q; q += (tiles[s] + NGROUPS - 1) / NGROUPS;
      }
      qp[NSPECIES] = q; }
    const int nquads = qp[NSPECIES];

    const int qpc = (nquads + gridDim.x - 1) / gridDim.x;
    const int q0 = blockIdx.x * qpc;
    const int q1 = min(q0 + qpc, nquads);

    int cur_s = -1;
    for (int q = q0; q < q1; q++) {
        int s = 3;
        if (q < qp[1]) s = 0; else if (q < qp[2]) s = 1; else if (q < qp[3]) s = 2;

        // ---- stage weights as fp16 on species change ----
        if (s != cur_s) {
            __syncthreads();
            for (int i = tid; i < FDIM * HDIM; i += NTHREADS) {
                int k = i >> 6, j = i & 63;
                W1h[k * SA + j] = __float2half_rn(W1[s * FDIM * HDIM + i]);
            }
            for (int i = tid; i < HDIM * HDIM; i += NTHREADS) {
                int k = i >> 6, j = i & 63;
                W2h[k * SA + j] = __float2half_rn(W2[s * HDIM * HDIM + i]);
            }
            if (tid < HDIM) {
                b1f[tid] = b1[s * HDIM + tid];
                b2f[tid] = b2[s * HDIM + tid];
                w3f[tid] = W3[s * HDIM + tid];
            }
            if (tid == 0) b3f[0] = b3[s];
            cur_s = s;
            __syncthreads();
        }

        const int tile = (q - qp[s]) * NGROUPS + g;
        if (tile >= tiles[s]) continue;
        const int start = beg[s] + tile * TM;
        const int m = min(TM, cnt[s] - tile * TM);

        // gather atom indices: this warp covers rows 16*wg .. 16*wg+15;
        // this lane serves atoms 16*wg + j*4 + aoff for j = 0..3
        int aidx[4];
        #pragma unroll
        for (int j = 0; j < 4; j++) {
            int r = 16 * wg + j * 4 + aoff;
            aidx[j] = g_sorted[start + (r < m ? r : m - 1)];
        }

        wmma::fragment<wmma::accumulator, 16, 16, 16, float> acc[2][2];
        #pragma unroll
        for (int mm = 0; mm < 2; mm++)
            #pragma unroll
            for (int nn = 0; nn < 2; nn++) wmma::fill_fragment(acc[mm][nn], 0.0f);

        // ---- layer 1: two 64-k chunks ----
        #pragma unroll 1
        for (int c = 0; c < 2; c++) {
            // 8-lanes-per-atom gather: each LDG.128 touches 4 lines (vs 32)
            #pragma unroll
            for (int i = 0; i < 8; i++) {
                const int j = i & 3;
                const int sub = i >> 2;        // which 32-float half of the chunk
                const float4 v = *(const float4*)(
                    feats + (size_t)aidx[j] * FDIM + c * 64 + sub * 32 + foff * 4);
                const int r = 16 * wg + j * 4 + aoff;
                unsigned* w = (unsigned*)(Bh + r * SA) + sub * 16 + foff * 2;
                w[0] = h2pack(v.x, v.y);
                w[1] = h2pack(v.z, v.w);
            }
            GBAR(barid);                           // A chunk visible

            #pragma unroll
            for (int ks = 0; ks < 4; ks++) {
                const int kg = c * 4 + ks;
                wmma::fragment<wmma::matrix_a, 16, 16, 16, __half, wmma::row_major> a[2];
                #pragma unroll
                for (int mm = 0; mm < 2; mm++)
                    wmma::load_matrix_sync(a[mm], Bh + (2 * wj + mm) * 16 * SA + ks * 16, SA);
                #pragma unroll
                for (int nn = 0; nn < 2; nn++) {
                    wmma::fragment<wmma::matrix_b, 16, 16, 16, __half, wmma::row_major> b;
                    wmma::load_matrix_sync(b, W1h + kg * 16 * SA + (2 * wi + nn) * 16, SA);
                    #pragma unroll
                    for (int mm = 0; mm < 2; mm++)
                        wmma::mma_sync(acc[mm][nn], a[mm], b, acc[mm][nn]);
                }
            }
            GBAR(barid);   // all warps' A loads done before BUF overwrite
        }

        // ---- O1 = acc -> smem (fp32, stride SA, aliases BUF) ----
        #pragma unroll
        for (int mm = 0; mm < 2; mm++)
            #pragma unroll
            for (int nn = 0; nn < 2; nn++)
                wmma::store_matrix_sync(Of + (2 * wj + mm) * 16 * SA + (2 * wi + nn) * 16,
                                        acc[mm][nn], SA, wmma::mem_row_major);
        GBAR(barid);

        // ---- act1: tanh(+b1) register-staged, cvt fp16 -> H in Bh ----
        {
            float vv[32];
            const float* orow = Of + row * SA + half * 32;
            const float* bb = b1f + half * 32;
            #pragma unroll
            for (int i = 0; i < 32; i++) vv[i] = fast_tanh(orow[i] + bb[i]);
            GBAR(barid);   // all O1 reads done before overwrite
            unsigned* hw = (unsigned*)(Bh + row * SA + half * 32);
            #pragma unroll
            for (int p = 0; p < 16; p++)
                hw[p] = h2pack(vv[2 * p], vv[2 * p + 1]);
        }
        GBAR(barid);

        // ---- layer 2: K = 64 ----
        #pragma unroll
        for (int mm = 0; mm < 2; mm++)
            #pragma unroll
            for (int nn = 0; nn < 2; nn++) wmma::fill_fragment(acc[mm][nn], 0.0f);
        #pragma unroll
        for (int ks = 0; ks < 4; ks++) {
            wmma::fragment<wmma::matrix_a, 16, 16, 16, __half, wmma::row_major> a[2];
            #pragma unroll
            for (int mm = 0; mm < 2; mm++)
                wmma::load_matrix_sync(a[mm], Bh + (2 * wj + mm) * 16 * SA + ks * 16, SA);
            #pragma unroll
            for (int nn = 0; nn < 2; nn++) {
                wmma::fragment<wmma::matrix_b, 16, 16, 16, __half, wmma::row_major> b;
                wmma::load_matrix_sync(b, W2h + ks * 16 * SA + (2 * wi + nn) * 16, SA);
                #pragma unroll
                for (int mm = 0; mm < 2; mm++)
                    wmma::mma_sync(acc[mm][nn], a[mm], b, acc[mm][nn]);
            }
        }
        GBAR(barid);   // all H reads done before O2 overwrite

        #pragma unroll
        for (int mm = 0; mm < 2; mm++)
            #pragma unroll
            for (int nn = 0; nn < 2; nn++)
                wmma::store_matrix_sync(Of + (2 * wj + mm) * 16 * SA + (2 * wi + nn) * 16,
                                        acc[mm][nn], SA, wmma::mem_row_major);
        GBAR(barid);

        // ---- epilogue: tanh(+b2) dot w3, combine halves ----
        {
            float e = 0.0f;
            const float* orow = Of + row * SA + half * 32;
            const float* bb = b2f + half * 32;
            const float* ww = w3f + half * 32;
            #pragma unroll
            for (int i = 0; i < 32; i++)
                e += fast_tanh(orow[i] + bb[i]) * ww[i];
            if (half == 1) EP[row] = e;
            GBAR(barid);
            if (half == 0 && row < m)
                out[g_sorted[start + row]] = e + EP[row] + b3f[0];
        }
        // next-iteration BUF writes are ordered by the next gather GBAR
    }
}

// ---------------- launch ----------------
extern "C" void kernel_launch(void* const* d_in, const int* in_sizes, int n_in,
                              void* d_out, int out_size)
{
    const float* feats   = (const float*)d_in[0];
    const void*  species = d_in[1];
    const float* W1 = (const float*)d_in[2];
    const float* b1 = (const float*)d_in[3];
    const float* W2 = (const float*)d_in[4];
    const float* b2 = (const float*)d_in[5];
    const float* W3 = (const float*)d_in[6];
    const float* b3 = (const float*)d_in[7];
    float* out = (float*)d_out;
    const int n = out_size;

    int dev = 0;
    cudaGetDevice(&dev);
    int nsm = 148;
    cudaDeviceGetAttribute(&nsm, cudaDevAttrMultiProcessorCount, dev);

    // launch order: init(1) hist(2) scatter(3) wmma(4) -> ncu captures #4
    init_kernel<<<1, 128>>>((const long long*)species, n);
    hist_kernel<<<nsm, 256>>>(species, n);
    scatter_kernel<<<nsm, 256>>>(species, n);

    cudaFuncSetAttribute(wmma_mlp_kernel,
                         cudaFuncAttributeMaxDynamicSharedMemorySize,
                         SMEM_BYTES);
    wmma_mlp_kernel<<<nsm, NTHREADS, SMEM_BYTES>>>(feats, W1, b1, W2, b2, W3, b3, out);
}